// round 1
// baseline (speedup 1.0000x reference)
#include <cuda_runtime.h>
#include <math.h>

// ---------------------------------------------------------------------------
// NeuralIF GCN pipeline, fp32.
//   N = in_sizes[0] (x elements), E = in_sizes[1] (edge_attr elements), L = 64
// Inputs (metadata order):
//  0 x[N,1] 1 edge_attr[E] 2 w_enc[1,64] 3 b_enc[64]
//  4 conv1_w[3,64,64] 5 conv1_b[3,64] 6 conv2_w[3,64,64] 7 conv2_b[3,64]
//  8 dec_w1[128,64] 9 dec_b1[64] 10 dec_w2[64,1] 11 dec_b2[1]
//  12 edge_row[E] (int32 OR int64 -- detected at runtime) 13 edge_col[E]
// Output: vals[E] float32
// ---------------------------------------------------------------------------

#define L 64
static const int NMAX = 100352;   // >= 100000
static const int EMAX = 1605632;  // >= 1600000

__device__ float g_deg[NMAX];
__device__ float g_cnt[NMAX];
__device__ float g_dinv[NMAX];
__device__ float g_rcp[NMAX];
__device__ float g_norm[EMAX];
__device__ float g_h[(size_t)NMAX * L];
__device__ float g_t0[(size_t)NMAX * L];  // hW / decoder A
__device__ float g_t1[(size_t)NMAX * L];  // agg / decoder B
__device__ int   g_is64;

// --- index dtype detection: int64 little-endian => odd 32-bit words are 0 ---
__global__ void k_detect(const unsigned int* er) {
    if (blockIdx.x == 0 && threadIdx.x == 0) {
        int ok = 1;
        #pragma unroll
        for (int i = 0; i < 64; i++)
            if (er[2 * i + 1] != 0u) ok = 0;
        g_is64 = ok;
    }
}

__device__ __forceinline__ int ld_idx(const void* p, int e, int is64) {
    if (is64) return (int)((const long long*)p)[e];
    return ((const int*)p)[e];
}

__global__ void k_zero(float* p, int n) {
    int i = blockIdx.x * blockDim.x + threadIdx.x;
    int stride = gridDim.x * blockDim.x;
    for (; i < n; i += stride) p[i] = 0.0f;
}

// deg[col] += attr ; cnt[col] += 1
__global__ void k_deg(const float* __restrict__ attr, const void* colp, int E) {
    int is64 = g_is64;
    int e = blockIdx.x * blockDim.x + threadIdx.x;
    if (e < E) {
        int c = ld_idx(colp, e, is64);
        atomicAdd(&g_deg[c], attr[e]);
        atomicAdd(&g_cnt[c], 1.0f);
    }
}

__global__ void k_dinv(int N) {
    int n = blockIdx.x * blockDim.x + threadIdx.x;
    if (n < N) {
        float d = g_deg[n];
        g_dinv[n] = (d > 0.0f) ? rsqrtf(fmaxf(d, 1e-30f)) : 0.0f;
        g_rcp[n]  = 1.0f / fmaxf(g_cnt[n], 1.0f);
    }
}

__global__ void k_norm(const float* __restrict__ attr, const void* rowp,
                       const void* colp, int E) {
    int is64 = g_is64;
    int e = blockIdx.x * blockDim.x + threadIdx.x;
    if (e < E) {
        int r = ld_idx(rowp, e, is64);
        int c = ld_idx(colp, e, is64);
        g_norm[e] = g_dinv[r] * attr[e] * g_dinv[c];
    }
}

// h[n][f] = x[n] * w_enc[f] + b_enc[f]
__global__ void k_enc(const float* __restrict__ x, const float* __restrict__ w,
                      const float* __restrict__ b, int N) {
    int i = blockIdx.x * blockDim.x + threadIdx.x;
    if (i < N * L) {
        int n = i >> 6, f = i & 63;
        g_h[i] = x[n] * w[f] + b[f];
    }
}

// Y[N,64] = X[N,64] @ W[64,64]   (64 rows per block, 256 threads)
__global__ void k_gemm64(const float* __restrict__ X, const float* __restrict__ W,
                         float* __restrict__ Y, int N) {
    __shared__ float Ws[64][64];
    __shared__ float Xs[64][65];
    int tid = threadIdx.x;
    for (int i = tid; i < 4096; i += 256) Ws[i >> 6][i & 63] = W[i];
    int row0 = blockIdx.x * 64;
    for (int i = tid; i < 4096; i += 256) {
        int r = i >> 6, k = i & 63;
        Xs[r][k] = (row0 + r < N) ? X[(size_t)(row0 + r) * L + k] : 0.0f;
    }
    __syncthreads();
    int lr = tid >> 2;   // local row 0..63
    int g  = tid & 3;    // output group of 16
    float acc[16];
    #pragma unroll
    for (int j = 0; j < 16; j++) acc[j] = 0.0f;
    #pragma unroll
    for (int k = 0; k < 64; k++) {
        float xv = Xs[lr][k];
        #pragma unroll
        for (int j = 0; j < 16; j++) acc[j] += xv * Ws[k][g * 16 + j];
    }
    int row = row0 + lr;
    if (row < N) {
        float* y = Y + (size_t)row * L + g * 16;
        #pragma unroll
        for (int j = 0; j < 16; j++) y[j] = acc[j];
    }
}

// scatter: agg[col] += hW[row] * norm[e]   (one warp per edge, 2 feats/lane)
__global__ void k_scatter(const float* __restrict__ hW, const void* rowp,
                          const void* colp, float* __restrict__ agg, int E) {
    int is64 = g_is64;
    int gt   = blockIdx.x * blockDim.x + threadIdx.x;
    int e    = gt >> 5;
    int lane = gt & 31;
    if (e < E) {
        int r = ld_idx(rowp, e, is64);
        int c = ld_idx(colp, e, is64);
        float nm = g_norm[e];
        const float2 v = *(const float2*)(hW + (size_t)r * L + lane * 2);
        float* dst = agg + (size_t)c * L + lane * 2;
        atomicAdd(dst,     v.x * nm);
        atomicAdd(dst + 1, v.y * nm);
    }
}

// h = relu(agg * rcp_cnt + b)
__global__ void k_finalize(const float* __restrict__ b, int N) {
    int i = blockIdx.x * blockDim.x + threadIdx.x;
    if (i < N * L) {
        int n = i >> 6, f = i & 63;
        float v = g_t1[i] * g_rcp[n] + b[f];
        g_h[i] = fmaxf(v, 0.0f);
    }
}

// decoder: out[e] = relu(A[r]+B[c]+b1) . w2 + b2 ; softplus on diag
__global__ void k_dec(const void* rowp, const void* colp,
                      const float* __restrict__ b1, const float* __restrict__ w2,
                      const float* __restrict__ b2, float* __restrict__ out, int E) {
    int is64 = g_is64;
    int gt   = blockIdx.x * blockDim.x + threadIdx.x;
    int e    = gt >> 5;
    int lane = gt & 31;
    if (e >= E) return;
    int r = ld_idx(rowp, e, is64);
    int c = ld_idx(colp, e, is64);
    const float* A = g_t0 + (size_t)r * L;
    const float* B = g_t1 + (size_t)c * L;
    float s = 0.0f;
    #pragma unroll
    for (int t = 0; t < 2; t++) {
        int f = lane + t * 32;
        float v = A[f] + B[f] + b1[f];
        v = fmaxf(v, 0.0f);
        s += v * w2[f];
    }
    #pragma unroll
    for (int off = 16; off; off >>= 1) s += __shfl_down_sync(0xffffffffu, s, off);
    if (lane == 0) {
        float val = s + b2[0];
        if (r == c) val = fmaxf(val, 0.0f) + log1pf(expf(-fabsf(val)));
        out[e] = val;
    }
}

extern "C" void kernel_launch(void* const* d_in, const int* in_sizes, int n_in,
                              void* d_out, int out_size) {
    const float* x        = (const float*)d_in[0];
    const float* eattr    = (const float*)d_in[1];
    const float* w_enc    = (const float*)d_in[2];
    const float* b_enc    = (const float*)d_in[3];
    const float* conv1_w  = (const float*)d_in[4];
    const float* conv1_b  = (const float*)d_in[5];
    const float* conv2_w  = (const float*)d_in[6];
    const float* conv2_b  = (const float*)d_in[7];
    const float* dec_w1   = (const float*)d_in[8];
    const float* dec_b1   = (const float*)d_in[9];
    const float* dec_w2   = (const float*)d_in[10];
    const float* dec_b2   = (const float*)d_in[11];
    const void*  rowp     = d_in[12];
    const void*  colp     = d_in[13];
    float* out = (float*)d_out;

    const int N = in_sizes[0];
    const int E = in_sizes[1];

    float *p_deg, *p_h, *p_t0, *p_t1;
    cudaGetSymbolAddress((void**)&p_deg, g_deg);
    cudaGetSymbolAddress((void**)&p_h,   g_h);
    cudaGetSymbolAddress((void**)&p_t0,  g_t0);
    cudaGetSymbolAddress((void**)&p_t1,  g_t1);
    float* p_cnt;
    cudaGetSymbolAddress((void**)&p_cnt, g_cnt);

    const int TB = 256;
    int eb  = (E + TB - 1) / TB;                 // 1 thread / edge
    int ew  = (int)(((long long)E * 32 + TB - 1) / TB);  // 1 warp / edge
    int nb  = (N + TB - 1) / TB;
    int nfb = (N * L + TB - 1) / TB;
    int gb  = (N + 63) / 64;

    // dtype detection first
    k_detect<<<1, 64>>>((const unsigned int*)rowp);

    // degree / count / norm
    k_zero<<<nb, TB>>>(p_deg, N);
    k_zero<<<nb, TB>>>(p_cnt, N);
    k_deg<<<eb, TB>>>(eattr, colp, E);
    k_dinv<<<nb, TB>>>(N);
    k_norm<<<eb, TB>>>(eattr, rowp, colp, E);

    // encoder
    k_enc<<<nfb, TB>>>(x, w_enc, b_enc, N);

    // 3 MP steps x 2 convs
    for (int i = 0; i < 3; i++) {
        const float* Ws[2] = { conv1_w + (size_t)i * 4096, conv2_w + (size_t)i * 4096 };
        const float* Bs[2] = { conv1_b + (size_t)i * 64,   conv2_b + (size_t)i * 64 };
        for (int j = 0; j < 2; j++) {
            k_gemm64<<<gb, TB>>>(p_h, Ws[j], p_t0, N);
            k_zero<<<nfb, TB>>>(p_t1, N * L);
            k_scatter<<<ew, TB>>>(p_t0, rowp, colp, p_t1, E);
            k_finalize<<<nfb, TB>>>(Bs[j], N);
        }
    }

    // decoder: A = h @ W1[0:64], B = h @ W1[64:128]
    k_gemm64<<<gb, TB>>>(p_h, dec_w1,        p_t0, N);
    k_gemm64<<<gb, TB>>>(p_h, dec_w1 + 4096, p_t1, N);
    k_dec<<<ew, TB>>>(rowp, colp, dec_b1, dec_w2, dec_b2, out, E);
}

// round 2
// speedup vs baseline: 1.7298x; 1.7298x over previous
#include <cuda_runtime.h>
#include <math.h>

// ---------------------------------------------------------------------------
// NeuralIF GCN pipeline, fp32, CSR gather-based (no feature atomics).
// ---------------------------------------------------------------------------

#define L 64
static const int NMAX = 100352;
static const int EMAX = 1605632;

__device__ float g_deg[NMAX];
__device__ float g_dinv[NMAX];
__device__ float g_rcp[NMAX];
__device__ float g_norm[EMAX];
__device__ int   g_cnti[NMAX];
__device__ int   g_offs[NMAX];    // incl-scan scratch, then exclusive offsets
__device__ int   g_cursor[NMAX];
__device__ int   g_bsums[1024];
__device__ uint2 g_csr[EMAX];     // .x = row idx, .y = norm bits
__device__ float g_h [(size_t)NMAX * L];
__device__ float g_t0[(size_t)NMAX * L];
__device__ float g_t1[(size_t)NMAX * L];
__device__ int   g_is64;

// --- index dtype detection: int64 LE => odd 32-bit words are all zero ---
__global__ void k_detect(const unsigned int* er) {
    if (blockIdx.x == 0 && threadIdx.x == 0) {
        int ok = 1;
        #pragma unroll
        for (int i = 0; i < 64; i++)
            if (er[2 * i + 1] != 0u) ok = 0;
        g_is64 = ok;
    }
}

__device__ __forceinline__ int ld_idx(const void* p, int e, int is64) {
    if (is64) return (int)((const long long*)p)[e];
    return ((const int*)p)[e];
}

__global__ void k_zero_f(float* p, int n) {
    int i = blockIdx.x * blockDim.x + threadIdx.x;
    if (i < n) p[i] = 0.0f;
}
__global__ void k_zero_i(int* p, int n) {
    int i = blockIdx.x * blockDim.x + threadIdx.x;
    if (i < n) p[i] = 0;
}

// deg[col] += attr ; cnt[col] += 1
__global__ void k_deg_cnt(const float* __restrict__ attr, const void* colp, int E) {
    int is64 = g_is64;
    int e = blockIdx.x * blockDim.x + threadIdx.x;
    if (e < E) {
        int c = ld_idx(colp, e, is64);
        atomicAdd(&g_deg[c], attr[e]);
        atomicAdd(&g_cnti[c], 1);
    }
}

__global__ void k_dinv(int N) {
    int n = blockIdx.x * blockDim.x + threadIdx.x;
    if (n < N) {
        float d = g_deg[n];
        g_dinv[n] = (d > 0.0f) ? rsqrtf(fmaxf(d, 1e-30f)) : 0.0f;
        int c = g_cnti[n];
        g_rcp[n] = 1.0f / fmaxf((float)c, 1.0f);
    }
}

__global__ void k_norm(const float* __restrict__ attr, const void* rowp,
                       const void* colp, int E) {
    int is64 = g_is64;
    int e = blockIdx.x * blockDim.x + threadIdx.x;
    if (e < E) {
        int r = ld_idx(rowp, e, is64);
        int c = ld_idx(colp, e, is64);
        g_norm[e] = g_dinv[r] * attr[e] * g_dinv[c];
    }
}

// ---------------- prefix scan over counts (1024 items / block) -------------
__global__ void k_scan1(int N) {
    __shared__ int wsum[8];
    int t = threadIdx.x;
    int base = blockIdx.x * 1024 + t * 4;
    int v0 = 0, v1 = 0, v2 = 0, v3 = 0;
    if (base + 0 < N) v0 = g_cnti[base + 0];
    if (base + 1 < N) v1 = g_cnti[base + 1];
    if (base + 2 < N) v2 = g_cnti[base + 2];
    if (base + 3 < N) v3 = g_cnti[base + 3];
    int s = v0 + v1 + v2 + v3;
    int lane = t & 31, warp = t >> 5;
    int x = s;
    #pragma unroll
    for (int o = 1; o < 32; o <<= 1) {
        int y = __shfl_up_sync(0xffffffffu, x, o);
        if (lane >= o) x += y;
    }
    if (lane == 31) wsum[warp] = x;
    __syncthreads();
    if (warp == 0 && lane < 8) {
        int w = wsum[lane];
        #pragma unroll
        for (int o = 1; o < 8; o <<= 1) {
            int y = __shfl_up_sync(0x000000ffu, w, o);
            if (lane >= o) w += y;
        }
        wsum[lane] = w;
    }
    __syncthreads();
    int excl = x - s + (warp > 0 ? wsum[warp - 1] : 0);
    int r = excl;
    r += v0; if (base + 0 < N) g_offs[base + 0] = r;
    r += v1; if (base + 1 < N) g_offs[base + 1] = r;
    r += v2; if (base + 2 < N) g_offs[base + 2] = r;
    r += v3; if (base + 3 < N) g_offs[base + 3] = r;
    if (t == 255) g_bsums[blockIdx.x] = excl + s;
}

__global__ void k_scan2(int nb) {
    if (threadIdx.x == 0 && blockIdx.x == 0) {
        int run = 0;
        for (int i = 0; i < nb; i++) { int t = g_bsums[i]; g_bsums[i] = run; run += t; }
    }
}

__global__ void k_scan3(int N) {
    int i = blockIdx.x * blockDim.x + threadIdx.x;
    if (i < N) {
        int excl = g_offs[i] + g_bsums[i >> 10] - g_cnti[i];
        g_offs[i] = excl;
        g_cursor[i] = excl;
    }
}

__global__ void k_csr_fill(const void* rowp, const void* colp, int E) {
    int is64 = g_is64;
    int e = blockIdx.x * blockDim.x + threadIdx.x;
    if (e < E) {
        int r = ld_idx(rowp, e, is64);
        int c = ld_idx(colp, e, is64);
        int p = atomicAdd(&g_cursor[c], 1);
        uint2 rec;
        rec.x = (unsigned int)r;
        rec.y = __float_as_uint(g_norm[e]);
        g_csr[p] = rec;
    }
}

// h[n][f] = x[n] * w_enc[f] + b_enc[f]
__global__ void k_enc(const float* __restrict__ x, const float* __restrict__ w,
                      const float* __restrict__ b, int N) {
    int i = blockIdx.x * blockDim.x + threadIdx.x;
    if (i < N * L) {
        int n = i >> 6, f = i & 63;
        g_h[i] = x[n] * w[f] + b[f];
    }
}

// ------------- fused layer: CSR gather-aggregate + GEMM + bias + relu ------
// agg[n] = (sum_{e in col n} norm_e * hin[row_e]) * rcp[n]
// hout[n] = relu(agg[n] @ W + b)
__global__ void __launch_bounds__(256)
k_agg_gemm(const float* __restrict__ hin, const float* __restrict__ W,
           const float* __restrict__ b, float* __restrict__ hout, int N) {
    __shared__ float Ws[64][64];
    __shared__ float As[64][66];
    int tid = threadIdx.x;
    for (int i = tid; i < 4096; i += 256) Ws[i >> 6][i & 63] = W[i];
    int n0 = blockIdx.x * 64;
    int warp = tid >> 5, lane = tid & 31;
    #pragma unroll 1
    for (int s = 0; s < 8; s++) {
        int ln = warp * 8 + s;
        int n = n0 + ln;
        float ax = 0.0f, ay = 0.0f;
        if (n < N) {
            int st = g_offs[n];
            int en = st + g_cnti[n];
            for (int k = st; k < en; k++) {
                uint2 rec = g_csr[k];                 // broadcast load
                float nm = __uint_as_float(rec.y);
                const float2 v = *(const float2*)(hin + ((size_t)rec.x << 6) + lane * 2);
                ax += v.x * nm;
                ay += v.y * nm;
            }
            float rcp = g_rcp[n];
            ax *= rcp; ay *= rcp;
        }
        As[ln][lane * 2]     = ax;
        As[ln][lane * 2 + 1] = ay;
    }
    __syncthreads();
    int lr = tid >> 2;   // local row 0..63
    int g  = tid & 3;    // 16-col group
    float acc[16];
    #pragma unroll
    for (int j = 0; j < 16; j++) acc[j] = 0.0f;
    #pragma unroll
    for (int k = 0; k < 64; k++) {
        float xv = As[lr][k];
        #pragma unroll
        for (int j = 0; j < 16; j++) acc[j] += xv * Ws[k][g * 16 + j];
    }
    int row = n0 + lr;
    if (row < N) {
        float* y = hout + ((size_t)row << 6) + g * 16;
        #pragma unroll
        for (int j = 0; j < 16; j++) y[j] = fmaxf(acc[j] + b[g * 16 + j], 0.0f);
    }
}

// Y[N,64] = X[N,64] @ W[64,64]  (decoder halves, no activation)
__global__ void __launch_bounds__(256)
k_gemm64(const float* __restrict__ X, const float* __restrict__ W,
         float* __restrict__ Y, int N) {
    __shared__ float Ws[64][64];
    __shared__ float Xs[64][65];
    int tid = threadIdx.x;
    for (int i = tid; i < 4096; i += 256) Ws[i >> 6][i & 63] = W[i];
    int row0 = blockIdx.x * 64;
    for (int i = tid; i < 4096; i += 256) {
        int r = i >> 6, k = i & 63;
        Xs[r][k] = (row0 + r < N) ? X[(size_t)(row0 + r) * L + k] : 0.0f;
    }
    __syncthreads();
    int lr = tid >> 2, g = tid & 3;
    float acc[16];
    #pragma unroll
    for (int j = 0; j < 16; j++) acc[j] = 0.0f;
    #pragma unroll
    for (int k = 0; k < 64; k++) {
        float xv = Xs[lr][k];
        #pragma unroll
        for (int j = 0; j < 16; j++) acc[j] += xv * Ws[k][g * 16 + j];
    }
    int row = row0 + lr;
    if (row < N) {
        float* y = Y + (size_t)row * L + g * 16;
        #pragma unroll
        for (int j = 0; j < 16; j++) y[j] = acc[j];
    }
}

// decoder: out[e] = relu(A[r]+B[c]+b1) . w2 + b2 ; softplus on diag
__global__ void k_dec(const void* rowp, const void* colp,
                      const float* __restrict__ b1, const float* __restrict__ w2,
                      const float* __restrict__ b2, float* __restrict__ out, int E) {
    int is64 = g_is64;
    int gt   = blockIdx.x * blockDim.x + threadIdx.x;
    int e    = gt >> 5;
    int lane = gt & 31;
    if (e >= E) return;
    int r = ld_idx(rowp, e, is64);
    int c = ld_idx(colp, e, is64);
    const float* A = g_t0 + (size_t)r * L;
    const float* B = g_t1 + (size_t)c * L;
    float s = 0.0f;
    #pragma unroll
    for (int t = 0; t < 2; t++) {
        int f = lane + t * 32;
        float v = A[f] + B[f] + b1[f];
        v = fmaxf(v, 0.0f);
        s += v * w2[f];
    }
    #pragma unroll
    for (int off = 16; off; off >>= 1) s += __shfl_down_sync(0xffffffffu, s, off);
    if (lane == 0) {
        float val = s + b2[0];
        if (r == c) val = fmaxf(val, 0.0f) + log1pf(expf(-fabsf(val)));
        out[e] = val;
    }
}

extern "C" void kernel_launch(void* const* d_in, const int* in_sizes, int n_in,
                              void* d_out, int out_size) {
    const float* x        = (const float*)d_in[0];
    const float* eattr    = (const float*)d_in[1];
    const float* w_enc    = (const float*)d_in[2];
    const float* b_enc    = (const float*)d_in[3];
    const float* conv1_w  = (const float*)d_in[4];
    const float* conv1_b  = (const float*)d_in[5];
    const float* conv2_w  = (const float*)d_in[6];
    const float* conv2_b  = (const float*)d_in[7];
    const float* dec_w1   = (const float*)d_in[8];
    const float* dec_b1   = (const float*)d_in[9];
    const float* dec_w2   = (const float*)d_in[10];
    const float* dec_b2   = (const float*)d_in[11];
    const void*  rowp     = d_in[12];
    const void*  colp     = d_in[13];
    float* out = (float*)d_out;

    const int N = in_sizes[0];
    const int E = in_sizes[1];

    float *p_deg, *p_h, *p_t0, *p_t1;
    int *p_cnti;
    cudaGetSymbolAddress((void**)&p_deg, g_deg);
    cudaGetSymbolAddress((void**)&p_h,   g_h);
    cudaGetSymbolAddress((void**)&p_t0,  g_t0);
    cudaGetSymbolAddress((void**)&p_t1,  g_t1);
    cudaGetSymbolAddress((void**)&p_cnti, g_cnti);

    const int TB = 256;
    int eb  = (E + TB - 1) / TB;
    int ew  = (int)(((long long)E * 32 + TB - 1) / TB);
    int nb  = (N + TB - 1) / TB;
    int nfb = (N * L + TB - 1) / TB;
    int gb  = (N + 63) / 64;
    int nsb = (N + 1023) / 1024;

    k_detect<<<1, 64>>>((const unsigned int*)rowp);

    // degree / count / norm
    k_zero_f<<<nb, TB>>>(p_deg, N);
    k_zero_i<<<nb, TB>>>(p_cnti, N);
    k_deg_cnt<<<eb, TB>>>(eattr, colp, E);
    k_dinv<<<nb, TB>>>(N);
    k_norm<<<eb, TB>>>(eattr, rowp, colp, E);

    // CSR build (by column)
    k_scan1<<<nsb, 256>>>(N);
    k_scan2<<<1, 32>>>(nsb);
    k_scan3<<<nb, TB>>>(N);
    k_csr_fill<<<eb, TB>>>(rowp, colp, E);

    // encoder
    k_enc<<<nfb, TB>>>(x, w_enc, b_enc, N);

    // 6 fused GCN layers (ping-pong h <-> t0)
    float* cur = p_h;
    float* nxt = p_t0;
    for (int i = 0; i < 3; i++) {
        k_agg_gemm<<<gb, TB>>>(cur, conv1_w + (size_t)i * 4096,
                               conv1_b + (size_t)i * 64, nxt, N);
        { float* t = cur; cur = nxt; nxt = t; }
        k_agg_gemm<<<gb, TB>>>(cur, conv2_w + (size_t)i * 4096,
                               conv2_b + (size_t)i * 64, nxt, N);
        { float* t = cur; cur = nxt; nxt = t; }
    }
    // after 6 layers cur == p_h

    // decoder: A = h @ W1[0:64], B = h @ W1[64:128]
    k_gemm64<<<gb, TB>>>(cur, dec_w1,        p_t0, N);
    k_gemm64<<<gb, TB>>>(cur, dec_w1 + 4096, p_t1, N);
    k_dec<<<ew, TB>>>(rowp, colp, dec_b1, dec_w2, dec_b2, out, E);
}

// round 3
// speedup vs baseline: 1.7469x; 1.0099x over previous
#include <cuda_runtime.h>
#include <math.h>

// ---------------------------------------------------------------------------
// NeuralIF GCN pipeline, fp32, CSR gather-based, ILP-unrolled aggregation.
// ---------------------------------------------------------------------------

#define L 64
static const int NMAX = 100352;
static const int EMAX = 1605632;

__device__ float g_deg[NMAX];
__device__ float g_dinv[NMAX];
__device__ float g_rcp[NMAX];
__device__ float g_norm[EMAX];
__device__ int   g_cnti[NMAX];
__device__ int   g_offs[NMAX];
__device__ int   g_cursor[NMAX];
__device__ int   g_bsums[1024];
__device__ uint2 g_csr[EMAX];     // .x = row idx, .y = norm bits
__device__ float g_h [(size_t)NMAX * L];
__device__ float g_t0[(size_t)NMAX * L];
__device__ float g_t1[(size_t)NMAX * L];
__device__ int   g_is64;

__global__ void k_detect(const unsigned int* er) {
    if (blockIdx.x == 0 && threadIdx.x == 0) {
        int ok = 1;
        #pragma unroll
        for (int i = 0; i < 64; i++)
            if (er[2 * i + 1] != 0u) ok = 0;
        g_is64 = ok;
    }
}

__device__ __forceinline__ int ld_idx(const void* p, int e, int is64) {
    if (is64) return (int)((const long long*)p)[e];
    return ((const int*)p)[e];
}

__global__ void k_zero_f(float* p, int n) {
    int i = blockIdx.x * blockDim.x + threadIdx.x;
    if (i < n) p[i] = 0.0f;
}
__global__ void k_zero_i(int* p, int n) {
    int i = blockIdx.x * blockDim.x + threadIdx.x;
    if (i < n) p[i] = 0;
}

__global__ void k_deg_cnt(const float* __restrict__ attr, const void* colp, int E) {
    int is64 = g_is64;
    int e = blockIdx.x * blockDim.x + threadIdx.x;
    if (e < E) {
        int c = ld_idx(colp, e, is64);
        atomicAdd(&g_deg[c], attr[e]);
        atomicAdd(&g_cnti[c], 1);
    }
}

__global__ void k_dinv(int N) {
    int n = blockIdx.x * blockDim.x + threadIdx.x;
    if (n < N) {
        float d = g_deg[n];
        g_dinv[n] = (d > 0.0f) ? rsqrtf(fmaxf(d, 1e-30f)) : 0.0f;
        g_rcp[n] = 1.0f / fmaxf((float)g_cnti[n], 1.0f);
    }
}

__global__ void k_norm(const float* __restrict__ attr, const void* rowp,
                       const void* colp, int E) {
    int is64 = g_is64;
    int e = blockIdx.x * blockDim.x + threadIdx.x;
    if (e < E) {
        int r = ld_idx(rowp, e, is64);
        int c = ld_idx(colp, e, is64);
        g_norm[e] = g_dinv[r] * attr[e] * g_dinv[c];
    }
}

// ---------------- prefix scan over counts -----------------------------------
__global__ void k_scan1(int N) {
    __shared__ int wsum[8];
    int t = threadIdx.x;
    int base = blockIdx.x * 1024 + t * 4;
    int v0 = 0, v1 = 0, v2 = 0, v3 = 0;
    if (base + 0 < N) v0 = g_cnti[base + 0];
    if (base + 1 < N) v1 = g_cnti[base + 1];
    if (base + 2 < N) v2 = g_cnti[base + 2];
    if (base + 3 < N) v3 = g_cnti[base + 3];
    int s = v0 + v1 + v2 + v3;
    int lane = t & 31, warp = t >> 5;
    int x = s;
    #pragma unroll
    for (int o = 1; o < 32; o <<= 1) {
        int y = __shfl_up_sync(0xffffffffu, x, o);
        if (lane >= o) x += y;
    }
    if (lane == 31) wsum[warp] = x;
    __syncthreads();
    if (warp == 0 && lane < 8) {
        int w = wsum[lane];
        #pragma unroll
        for (int o = 1; o < 8; o <<= 1) {
            int y = __shfl_up_sync(0x000000ffu, w, o);
            if (lane >= o) w += y;
        }
        wsum[lane] = w;
    }
    __syncthreads();
    int excl = x - s + (warp > 0 ? wsum[warp - 1] : 0);
    int r = excl;
    r += v0; if (base + 0 < N) g_offs[base + 0] = r;
    r += v1; if (base + 1 < N) g_offs[base + 1] = r;
    r += v2; if (base + 2 < N) g_offs[base + 2] = r;
    r += v3; if (base + 3 < N) g_offs[base + 3] = r;
    if (t == 255) g_bsums[blockIdx.x] = excl + s;
}

__global__ void k_scan2(int nb) {
    if (threadIdx.x == 0 && blockIdx.x == 0) {
        int run = 0;
        for (int i = 0; i < nb; i++) { int t = g_bsums[i]; g_bsums[i] = run; run += t; }
    }
}

__global__ void k_scan3(int N) {
    int i = blockIdx.x * blockDim.x + threadIdx.x;
    if (i < N) {
        int excl = g_offs[i] + g_bsums[i >> 10] - g_cnti[i];
        g_offs[i] = excl;
        g_cursor[i] = excl;
    }
}

__global__ void k_csr_fill(const void* rowp, const void* colp, int E) {
    int is64 = g_is64;
    int e = blockIdx.x * blockDim.x + threadIdx.x;
    if (e < E) {
        int r = ld_idx(rowp, e, is64);
        int c = ld_idx(colp, e, is64);
        int p = atomicAdd(&g_cursor[c], 1);
        uint2 rec;
        rec.x = (unsigned int)r;
        rec.y = __float_as_uint(g_norm[e]);
        g_csr[p] = rec;
    }
}

__global__ void k_enc(const float* __restrict__ x, const float* __restrict__ w,
                      const float* __restrict__ b, int N) {
    int i = blockIdx.x * blockDim.x + threadIdx.x;
    if (i < N * L) {
        int n = i >> 6, f = i & 63;
        g_h[i] = x[n] * w[f] + b[f];
    }
}

// ------------- fused layer: CSR gather-aggregate + GEMM + bias + relu ------
__global__ void __launch_bounds__(256)
k_agg_gemm(const float* __restrict__ hin, const float* __restrict__ W,
           const float* __restrict__ b, float* __restrict__ hout, int N) {
    __shared__ float Ws[64][64];
    __shared__ float As[64][66];
    int tid = threadIdx.x;
    for (int i = tid; i < 4096; i += 256) Ws[i >> 6][i & 63] = W[i];
    int n0 = blockIdx.x * 64;
    int warp = tid >> 5, lane = tid & 31;
    int lane2 = lane * 2;
    #pragma unroll 1
    for (int s = 0; s < 8; s++) {
        int ln = warp * 8 + s;
        int n = n0 + ln;
        float ax = 0.0f, ay = 0.0f;
        if (n < N) {
            int st = g_offs[n];
            int en = st + g_cnti[n];
            int k = st;
            #pragma unroll 1
            for (; k + 4 <= en; k += 4) {
                uint2 e0 = g_csr[k + 0];
                uint2 e1 = g_csr[k + 1];
                uint2 e2 = g_csr[k + 2];
                uint2 e3 = g_csr[k + 3];
                float2 v0 = *(const float2*)(hin + ((size_t)e0.x << 6) + lane2);
                float2 v1 = *(const float2*)(hin + ((size_t)e1.x << 6) + lane2);
                float2 v2 = *(const float2*)(hin + ((size_t)e2.x << 6) + lane2);
                float2 v3 = *(const float2*)(hin + ((size_t)e3.x << 6) + lane2);
                float n0f = __uint_as_float(e0.y), n1f = __uint_as_float(e1.y);
                float n2f = __uint_as_float(e2.y), n3f = __uint_as_float(e3.y);
                ax += v0.x * n0f; ay += v0.y * n0f;
                ax += v1.x * n1f; ay += v1.y * n1f;
                ax += v2.x * n2f; ay += v2.y * n2f;
                ax += v3.x * n3f; ay += v3.y * n3f;
            }
            #pragma unroll 1
            for (; k < en; k++) {
                uint2 rec = g_csr[k];
                float nm = __uint_as_float(rec.y);
                float2 v = *(const float2*)(hin + ((size_t)rec.x << 6) + lane2);
                ax += v.x * nm; ay += v.y * nm;
            }
            float rcp = g_rcp[n];
            ax *= rcp; ay *= rcp;
        }
        As[ln][lane2]     = ax;
        As[ln][lane2 + 1] = ay;
    }
    __syncthreads();
    int lr = tid >> 2;
    int g  = tid & 3;
    float acc[16];
    #pragma unroll
    for (int j = 0; j < 16; j++) acc[j] = 0.0f;
    #pragma unroll
    for (int k = 0; k < 64; k++) {
        float xv = As[lr][k];
        #pragma unroll
        for (int j = 0; j < 16; j++) acc[j] += xv * Ws[k][g * 16 + j];
    }
    int row = n0 + lr;
    if (row < N) {
        float* y = hout + ((size_t)row << 6) + g * 16;
        #pragma unroll
        for (int j = 0; j < 16; j++) y[j] = fmaxf(acc[j] + b[g * 16 + j], 0.0f);
    }
}

// Y[N,64] = X[N,64] @ W[64,64]
__global__ void __launch_bounds__(256)
k_gemm64(const float* __restrict__ X, const float* __restrict__ W,
         float* __restrict__ Y, int N) {
    __shared__ float Ws[64][64];
    __shared__ float Xs[64][65];
    int tid = threadIdx.x;
    for (int i = tid; i < 4096; i += 256) Ws[i >> 6][i & 63] = W[i];
    int row0 = blockIdx.x * 64;
    for (int i = tid; i < 4096; i += 256) {
        int r = i >> 6, k = i & 63;
        Xs[r][k] = (row0 + r < N) ? X[(size_t)(row0 + r) * L + k] : 0.0f;
    }
    __syncthreads();
    int lr = tid >> 2, g = tid & 3;
    float acc[16];
    #pragma unroll
    for (int j = 0; j < 16; j++) acc[j] = 0.0f;
    #pragma unroll
    for (int k = 0; k < 64; k++) {
        float xv = Xs[lr][k];
        #pragma unroll
        for (int j = 0; j < 16; j++) acc[j] += xv * Ws[k][g * 16 + j];
    }
    int row = row0 + lr;
    if (row < N) {
        float* y = Y + (size_t)row * L + g * 16;
        #pragma unroll
        for (int j = 0; j < 16; j++) y[j] = acc[j];
    }
}

// decoder: out[e] = relu(A[r]+B[c]+b1) . w2 + b2 ; softplus on diag
#define DEC_EPW 8   // edges per warp
__global__ void __launch_bounds__(256)
k_dec(const void* rowp, const void* colp,
      const float* __restrict__ b1, const float* __restrict__ w2,
      const float* __restrict__ b2, float* __restrict__ out, int E) {
    int is64 = g_is64;
    int gw   = (blockIdx.x * blockDim.x + threadIdx.x) >> 5;
    int lane = threadIdx.x & 31;
    int lane2 = lane * 2;
    float2 bias = *(const float2*)(b1 + lane2);
    float2 w    = *(const float2*)(w2 + lane2);
    float  bout = b2[0];
    int e0 = gw * DEC_EPW;
    int e1 = e0 + DEC_EPW < E ? e0 + DEC_EPW : E;
    #pragma unroll 1
    for (int e = e0; e < e1; e++) {
        int r = ld_idx(rowp, e, is64);
        int c = ld_idx(colp, e, is64);
        float2 a  = *(const float2*)(g_t0 + ((size_t)r << 6) + lane2);
        float2 bb = *(const float2*)(g_t1 + ((size_t)c << 6) + lane2);
        float s = fmaxf(a.x + bb.x + bias.x, 0.0f) * w.x
                + fmaxf(a.y + bb.y + bias.y, 0.0f) * w.y;
        #pragma unroll
        for (int off = 16; off; off >>= 1) s += __shfl_down_sync(0xffffffffu, s, off);
        if (lane == 0) {
            float val = s + bout;
            if (r == c) val = fmaxf(val, 0.0f) + log1pf(expf(-fabsf(val)));
            out[e] = val;
        }
    }
}

extern "C" void kernel_launch(void* const* d_in, const int* in_sizes, int n_in,
                              void* d_out, int out_size) {
    const float* x        = (const float*)d_in[0];
    const float* eattr    = (const float*)d_in[1];
    const float* w_enc    = (const float*)d_in[2];
    const float* b_enc    = (const float*)d_in[3];
    const float* conv1_w  = (const float*)d_in[4];
    const float* conv1_b  = (const float*)d_in[5];
    const float* conv2_w  = (const float*)d_in[6];
    const float* conv2_b  = (const float*)d_in[7];
    const float* dec_w1   = (const float*)d_in[8];
    const float* dec_b1   = (const float*)d_in[9];
    const float* dec_w2   = (const float*)d_in[10];
    const float* dec_b2   = (const float*)d_in[11];
    const void*  rowp     = d_in[12];
    const void*  colp     = d_in[13];
    float* out = (float*)d_out;

    const int N = in_sizes[0];
    const int E = in_sizes[1];

    float *p_deg, *p_h, *p_t0, *p_t1;
    int *p_cnti;
    cudaGetSymbolAddress((void**)&p_deg, g_deg);
    cudaGetSymbolAddress((void**)&p_h,   g_h);
    cudaGetSymbolAddress((void**)&p_t0,  g_t0);
    cudaGetSymbolAddress((void**)&p_t1,  g_t1);
    cudaGetSymbolAddress((void**)&p_cnti, g_cnti);

    const int TB = 256;
    int eb  = (E + TB - 1) / TB;
    int nb  = (N + TB - 1) / TB;
    int nfb = (N * L + TB - 1) / TB;
    int gb  = (N + 63) / 64;
    int nsb = (N + 1023) / 1024;
    int db  = (int)(((long long)E + DEC_EPW * 8 - 1) / (DEC_EPW * 8)); // 8 warps/block

    k_detect<<<1, 64>>>((const unsigned int*)rowp);

    k_zero_f<<<nb, TB>>>(p_deg, N);
    k_zero_i<<<nb, TB>>>(p_cnti, N);
    k_deg_cnt<<<eb, TB>>>(eattr, colp, E);
    k_dinv<<<nb, TB>>>(N);
    k_norm<<<eb, TB>>>(eattr, rowp, colp, E);

    k_scan1<<<nsb, 256>>>(N);
    k_scan2<<<1, 32>>>(nsb);
    k_scan3<<<nb, TB>>>(N);
    k_csr_fill<<<eb, TB>>>(rowp, colp, E);

    k_enc<<<nfb, TB>>>(x, w_enc, b_enc, N);

    float* cur = p_h;
    float* nxt = p_t0;
    for (int i = 0; i < 3; i++) {
        k_agg_gemm<<<gb, TB>>>(cur, conv1_w + (size_t)i * 4096,
                               conv1_b + (size_t)i * 64, nxt, N);
        { float* t = cur; cur = nxt; nxt = t; }
        k_agg_gemm<<<gb, TB>>>(cur, conv2_w + (size_t)i * 4096,
                               conv2_b + (size_t)i * 64, nxt, N);
        { float* t = cur; cur = nxt; nxt = t; }
    }

    k_gemm64<<<gb, TB>>>(cur, dec_w1,        p_t0, N);
    k_gemm64<<<gb, TB>>>(cur, dec_w1 + 4096, p_t1, N);
    k_dec<<<db, TB>>>(rowp, colp, dec_b1, dec_w2, dec_b2, out, E);
}

// round 4
// speedup vs baseline: 4.0269x; 2.3052x over previous
#include <cuda_runtime.h>
#include <math.h>

#define L 64
static const int NMAX = 100352;
static const int EMAX = 1605632;

__device__ __align__(16) float g_deg[NMAX];
__device__ __align__(16) float g_dinv[NMAX];
__device__ __align__(16) float g_rcp[NMAX];
__device__ __align__(16) float g_norm[EMAX];
__device__ int   g_cnti[NMAX];
__device__ int   g_offs[NMAX];
__device__ int   g_cursor[NMAX];
__device__ int   g_bsums[1024];
__device__ __align__(16) uint2 g_csr[EMAX];   // .x = row idx, .y = norm bits
__device__ __align__(16) float g_h [(size_t)NMAX * L];
__device__ __align__(16) float g_t0[(size_t)NMAX * L];
__device__ __align__(16) float g_t1[(size_t)NMAX * L];
__device__ int   g_is64;

__global__ void k_detect(const unsigned int* er) {
    if (blockIdx.x == 0 && threadIdx.x == 0) {
        int ok = 1;
        #pragma unroll
        for (int i = 0; i < 64; i++)
            if (er[2 * i + 1] != 0u) ok = 0;
        g_is64 = ok;
    }
}

__device__ __forceinline__ int ld_idx(const void* p, int e, int is64) {
    if (is64) return (int)((const long long*)p)[e];
    return ((const int*)p)[e];
}

__global__ void k_zero2(float* pf, int* pi, int n) {
    int i = blockIdx.x * blockDim.x + threadIdx.x;
    if (i < n) { pf[i] = 0.0f; pi[i] = 0; }
}

__global__ void k_deg_cnt(const float* __restrict__ attr, const void* colp, int E) {
    int is64 = g_is64;
    int e = blockIdx.x * blockDim.x + threadIdx.x;
    if (e < E) {
        int c = ld_idx(colp, e, is64);
        atomicAdd(&g_deg[c], attr[e]);
        atomicAdd(&g_cnti[c], 1);
    }
}

__global__ void k_dinv(int N) {
    int n = blockIdx.x * blockDim.x + threadIdx.x;
    if (n < N) {
        float d = g_deg[n];
        g_dinv[n] = (d > 0.0f) ? rsqrtf(fmaxf(d, 1e-30f)) : 0.0f;
        g_rcp[n] = 1.0f / fmaxf((float)g_cnti[n], 1.0f);
    }
}

__global__ void k_norm(const float* __restrict__ attr, const void* rowp,
                       const void* colp, int E) {
    int is64 = g_is64;
    int e = blockIdx.x * blockDim.x + threadIdx.x;
    if (e < E) {
        int r = ld_idx(rowp, e, is64);
        int c = ld_idx(colp, e, is64);
        g_norm[e] = g_dinv[r] * attr[e] * g_dinv[c];
    }
}

// ---------------- prefix scan over counts -----------------------------------
__global__ void k_scan1(int N) {
    __shared__ int wsum[8];
    int t = threadIdx.x;
    int base = blockIdx.x * 1024 + t * 4;
    int v0 = 0, v1 = 0, v2 = 0, v3 = 0;
    if (base + 0 < N) v0 = g_cnti[base + 0];
    if (base + 1 < N) v1 = g_cnti[base + 1];
    if (base + 2 < N) v2 = g_cnti[base + 2];
    if (base + 3 < N) v3 = g_cnti[base + 3];
    int s = v0 + v1 + v2 + v3;
    int lane = t & 31, warp = t >> 5;
    int x = s;
    #pragma unroll
    for (int o = 1; o < 32; o <<= 1) {
        int y = __shfl_up_sync(0xffffffffu, x, o);
        if (lane >= o) x += y;
    }
    if (lane == 31) wsum[warp] = x;
    __syncthreads();
    if (warp == 0 && lane < 8) {
        int w = wsum[lane];
        #pragma unroll
        for (int o = 1; o < 8; o <<= 1) {
            int y = __shfl_up_sync(0x000000ffu, w, o);
            if (lane >= o) w += y;
        }
        wsum[lane] = w;
    }
    __syncthreads();
    int excl = x - s + (warp > 0 ? wsum[warp - 1] : 0);
    int r = excl;
    r += v0; if (base + 0 < N) g_offs[base + 0] = r;
    r += v1; if (base + 1 < N) g_offs[base + 1] = r;
    r += v2; if (base + 2 < N) g_offs[base + 2] = r;
    r += v3; if (base + 3 < N) g_offs[base + 3] = r;
    if (t == 255) g_bsums[blockIdx.x] = excl + s;
}

__global__ void k_scan2(int nb) {
    if (threadIdx.x == 0 && blockIdx.x == 0) {
        int run = 0;
        for (int i = 0; i < nb; i++) { int t = g_bsums[i]; g_bsums[i] = run; run += t; }
    }
}

__global__ void k_scan3(int N) {
    int i = blockIdx.x * blockDim.x + threadIdx.x;
    if (i < N) {
        int excl = g_offs[i] + g_bsums[i >> 10] - g_cnti[i];
        g_offs[i] = excl;
        g_cursor[i] = excl;
    }
}

__global__ void k_csr_fill(const void* rowp, const void* colp, int E) {
    int is64 = g_is64;
    int e = blockIdx.x * blockDim.x + threadIdx.x;
    if (e < E) {
        int r = ld_idx(rowp, e, is64);
        int c = ld_idx(colp, e, is64);
        int p = atomicAdd(&g_cursor[c], 1);
        uint2 rec;
        rec.x = (unsigned int)r;
        rec.y = __float_as_uint(g_norm[e]);
        g_csr[p] = rec;
    }
}

__global__ void k_enc(const float* __restrict__ x, const float* __restrict__ w,
                      const float* __restrict__ b, int N) {
    int i = blockIdx.x * blockDim.x + threadIdx.x;
    if (i < N * L) {
        int n = i >> 6, f = i & 63;
        g_h[i] = x[n] * w[f] + b[f];
    }
}

// ---- aggregation: agg[n] = rcp[n] * sum_e norm_e * hin[row_e]  (warp/node) --
__global__ void __launch_bounds__(256)
k_agg(const float* __restrict__ hin, float* __restrict__ aggo, int N) {
    int warp = threadIdx.x >> 5, lane = threadIdx.x & 31;
    int n = blockIdx.x * 8 + warp;
    if (n >= N) return;
    int lane2 = lane * 2;
    int st = g_offs[n];
    int en = st + g_cnti[n];
    float ax0 = 0.f, ay0 = 0.f, ax1 = 0.f, ay1 = 0.f;
    int k = st;
    #pragma unroll 1
    for (; k + 4 <= en; k += 4) {
        uint2 e0 = g_csr[k + 0];
        uint2 e1 = g_csr[k + 1];
        uint2 e2 = g_csr[k + 2];
        uint2 e3 = g_csr[k + 3];
        float2 v0 = *(const float2*)(hin + ((size_t)e0.x << 6) + lane2);
        float2 v1 = *(const float2*)(hin + ((size_t)e1.x << 6) + lane2);
        float2 v2 = *(const float2*)(hin + ((size_t)e2.x << 6) + lane2);
        float2 v3 = *(const float2*)(hin + ((size_t)e3.x << 6) + lane2);
        float f0 = __uint_as_float(e0.y), f1 = __uint_as_float(e1.y);
        float f2 = __uint_as_float(e2.y), f3 = __uint_as_float(e3.y);
        ax0 += v0.x * f0; ay0 += v0.y * f0;
        ax1 += v1.x * f1; ay1 += v1.y * f1;
        ax0 += v2.x * f2; ay0 += v2.y * f2;
        ax1 += v3.x * f3; ay1 += v3.y * f3;
    }
    #pragma unroll 1
    for (; k < en; k++) {
        uint2 rec = g_csr[k];
        float nm = __uint_as_float(rec.y);
        float2 v = *(const float2*)(hin + ((size_t)rec.x << 6) + lane2);
        ax0 += v.x * nm; ay0 += v.y * nm;
    }
    float rcp = g_rcp[n];
    float2 o;
    o.x = (ax0 + ax1) * rcp;
    o.y = (ay0 + ay1) * rcp;
    *(float2*)(aggo + ((size_t)n << 6) + lane2) = o;
}

// ---- GEMM: Y[64 rows] = X @ W (+bias, relu). Register-blocked 4x4. ---------
// Stores unconditionally: buffers are NMAX=100352 rows, grid*64 <= NMAX.
template<bool RELU>
__global__ void __launch_bounds__(256)
k_gemm(const float* __restrict__ X, const float* __restrict__ W,
       const float* __restrict__ bias, float* __restrict__ Y) {
    __shared__ float Ws[64][64];
    __shared__ float Xs[64][68];
    int tid = threadIdx.x;
    const float4* W4 = (const float4*)W;
    #pragma unroll
    for (int i = 0; i < 4; i++) {
        int idx = tid + i * 256;
        float4 v = W4[idx];
        *(float4*)&Ws[idx >> 4][(idx & 15) * 4] = v;
    }
    size_t base = (size_t)blockIdx.x * (64 * 64);
    const float4* X4 = (const float4*)(X + base);
    #pragma unroll
    for (int i = 0; i < 4; i++) {
        int idx = tid + i * 256;
        float4 v = X4[idx];
        *(float4*)&Xs[idx >> 4][(idx & 15) * 4] = v;
    }
    __syncthreads();
    int tr = (tid >> 4) * 4;
    int tc = (tid & 15) * 4;
    float a00=0,a01=0,a02=0,a03=0, a10=0,a11=0,a12=0,a13=0;
    float a20=0,a21=0,a22=0,a23=0, a30=0,a31=0,a32=0,a33=0;
    #pragma unroll
    for (int k = 0; k < 64; k++) {
        float4 w = *(const float4*)&Ws[k][tc];
        float x0 = Xs[tr + 0][k];
        float x1 = Xs[tr + 1][k];
        float x2 = Xs[tr + 2][k];
        float x3 = Xs[tr + 3][k];
        a00 += x0*w.x; a01 += x0*w.y; a02 += x0*w.z; a03 += x0*w.w;
        a10 += x1*w.x; a11 += x1*w.y; a12 += x1*w.z; a13 += x1*w.w;
        a20 += x2*w.x; a21 += x2*w.y; a22 += x2*w.z; a23 += x2*w.w;
        a30 += x3*w.x; a31 += x3*w.y; a32 += x3*w.z; a33 += x3*w.w;
    }
    float4 bb = make_float4(0.f, 0.f, 0.f, 0.f);
    if (bias) bb = *(const float4*)(bias + tc);
    float* y0 = Y + base + (size_t)tr * 64 + tc;
    float4 o;
    #define EMIT(r, c0, c1, c2, c3)                                        \
        o.x = c0 + bb.x; o.y = c1 + bb.y; o.z = c2 + bb.z; o.w = c3 + bb.w;\
        if (RELU) { o.x = fmaxf(o.x, 0.f); o.y = fmaxf(o.y, 0.f);          \
                    o.z = fmaxf(o.z, 0.f); o.w = fmaxf(o.w, 0.f); }        \
        *(float4*)(y0 + (r) * 64) = o;
    EMIT(0, a00, a01, a02, a03)
    EMIT(1, a10, a11, a12, a13)
    EMIT(2, a20, a21, a22, a23)
    EMIT(3, a30, a31, a32, a33)
    #undef EMIT
}

// ---- decoder: out[e] = relu(A[r]+B[c]+b1).w2 + b2 ; softplus on diag -------
#define DEC_EPW 8
__global__ void __launch_bounds__(256)
k_dec(const void* rowp, const void* colp,
      const float* __restrict__ b1, const float* __restrict__ w2,
      const float* __restrict__ b2, float* __restrict__ out, int E) {
    int is64 = g_is64;
    int gw   = (blockIdx.x * blockDim.x + threadIdx.x) >> 5;
    int lane = threadIdx.x & 31;
    int lane2 = lane * 2;
    float2 bias = *(const float2*)(b1 + lane2);
    float2 w    = *(const float2*)(w2 + lane2);
    float  bout = b2[0];
    int e0 = gw * DEC_EPW;
    if (e0 >= E) return;
    int m = E - e0; if (m > DEC_EPW) m = DEC_EPW;

    int   rr[DEC_EPW], cc[DEC_EPW];
    float s[DEC_EPW];
    // phase 1: independent loads + per-lane partial sums (MLP across edges)
    #pragma unroll
    for (int j = 0; j < DEC_EPW; j++) {
        if (j < m) {
            int r = ld_idx(rowp, e0 + j, is64);
            int c = ld_idx(colp, e0 + j, is64);
            rr[j] = r; cc[j] = c;
            float2 a  = *(const float2*)(g_t0 + ((size_t)r << 6) + lane2);
            float2 bb = *(const float2*)(g_t1 + ((size_t)c << 6) + lane2);
            s[j] = fmaxf(a.x + bb.x + bias.x, 0.f) * w.x
                 + fmaxf(a.y + bb.y + bias.y, 0.f) * w.y;
        }
    }
    // phase 2: reductions
    #pragma unroll
    for (int j = 0; j < DEC_EPW; j++) {
        if (j < m) {
            float v = s[j];
            #pragma unroll
            for (int off = 16; off; off >>= 1)
                v += __shfl_down_sync(0xffffffffu, v, off);
            if (lane == 0) {
                float val = v + bout;
                if (rr[j] == cc[j])
                    val = fmaxf(val, 0.f) + log1pf(expf(-fabsf(val)));
                out[e0 + j] = val;
            }
        }
    }
}

extern "C" void kernel_launch(void* const* d_in, const int* in_sizes, int n_in,
                              void* d_out, int out_size) {
    const float* x        = (const float*)d_in[0];
    const float* eattr    = (const float*)d_in[1];
    const float* w_enc    = (const float*)d_in[2];
    const float* b_enc    = (const float*)d_in[3];
    const float* conv1_w  = (const float*)d_in[4];
    const float* conv1_b  = (const float*)d_in[5];
    const float* conv2_w  = (const float*)d_in[6];
    const float* conv2_b  = (const float*)d_in[7];
    const float* dec_w1   = (const float*)d_in[8];
    const float* dec_b1   = (const float*)d_in[9];
    const float* dec_w2   = (const float*)d_in[10];
    const float* dec_b2   = (const float*)d_in[11];
    const void*  rowp     = d_in[12];
    const void*  colp     = d_in[13];
    float* out = (float*)d_out;

    const int N = in_sizes[0];
    const int E = in_sizes[1];

    float *p_deg, *p_h, *p_t0, *p_t1;
    int *p_cnti;
    cudaGetSymbolAddress((void**)&p_deg, g_deg);
    cudaGetSymbolAddress((void**)&p_h,   g_h);
    cudaGetSymbolAddress((void**)&p_t0,  g_t0);
    cudaGetSymbolAddress((void**)&p_t1,  g_t1);
    cudaGetSymbolAddress((void**)&p_cnti, g_cnti);

    const int TB = 256;
    int eb  = (E + TB - 1) / TB;
    int nb  = (N + TB - 1) / TB;
    int nfb = (N * L + TB - 1) / TB;
    int gb  = (N + 63) / 64;
    int ab  = (N + 7) / 8;
    int nsb = (N + 1023) / 1024;
    int db  = (int)(((long long)E + DEC_EPW * 8 - 1) / (DEC_EPW * 8));

    k_detect<<<1, 64>>>((const unsigned int*)rowp);

    k_zero2<<<nb, TB>>>(p_deg, p_cnti, N);
    k_deg_cnt<<<eb, TB>>>(eattr, colp, E);
    k_dinv<<<nb, TB>>>(N);
    k_norm<<<eb, TB>>>(eattr, rowp, colp, E);

    k_scan1<<<nsb, 256>>>(N);
    k_scan2<<<1, 32>>>(nsb);
    k_scan3<<<nb, TB>>>(N);
    k_csr_fill<<<eb, TB>>>(rowp, colp, E);

    k_enc<<<nfb, TB>>>(x, w_enc, b_enc, N);

    // 6 GCN layers: agg (cur -> t1), gemm+bias+relu (t1 -> nxt)
    float* cur = p_h;
    float* nxt = p_t0;
    for (int i = 0; i < 3; i++) {
        k_agg<<<ab, TB>>>(cur, p_t1, N);
        k_gemm<true><<<gb, TB>>>(p_t1, conv1_w + (size_t)i * 4096,
                                 conv1_b + (size_t)i * 64, nxt);
        { float* t = cur; cur = nxt; nxt = t; }
        k_agg<<<ab, TB>>>(cur, p_t1, N);
        k_gemm<true><<<gb, TB>>>(p_t1, conv2_w + (size_t)i * 4096,
                                 conv2_b + (size_t)i * 64, nxt);
        { float* t = cur; cur = nxt; nxt = t; }
    }
    // cur == p_h after 6 layers

    k_gemm<false><<<gb, TB>>>(cur, dec_w1,        (const float*)0, p_t0);
    k_gemm<false><<<gb, TB>>>(cur, dec_w1 + 4096, (const float*)0, p_t1);
    k_dec<<<db, TB>>>(rowp, colp, dec_b1, dec_w2, dec_b2, out, E);
}